// round 11
// baseline (speedup 1.0000x reference)
#include <cuda_runtime.h>
#include <math.h>

// Problem constants
#define U_N 512
#define P_N 1024
#define N_N 1536
#define D_D 128
#define H_H 256
#define E_E 98304
#define NB  148          // persistent grid size (all co-resident: 1 block/SM)
#define NT  256

// ---------------- scratch (static __device__, no allocs) ----------------
__device__ int   g_deg[N_N];
__device__ float g_dis[N_N];
__device__ int   g_off[N_N + 1];
__device__ int   g_rank[E_E];
__device__ int   g_csrc[E_E];
__device__ float g_cnorm[E_E];
__device__ float g_x0[N_N * D_D];
__device__ float g_h0[N_N * H_H];
__device__ float g_h1[N_N * H_H];
__device__ float g_h2[N_N * H_H];
__device__ float g_xa[N_N * H_H];
__device__ float g_xb[N_N * H_H];
__device__ float g_xc[N_N * H_H];
__device__ float g_WcU[H_H * H_H];   // Wu @ Wq1_top   [256,256]
__device__ float g_WcP[H_H * H_H];   // Wp @ Wq1_bot   [256,256]
__device__ float g_bcU[H_H];
__device__ float g_bcP[H_H];
__device__ float g_A[U_N * H_H];
__device__ float g_B[P_N * H_H];

// ---------------- grid barrier (sense reversing, replay-safe) ----------------
__device__ int           g_bcount;
__device__ volatile int  g_bsense;

__device__ __forceinline__ void gsync(int* lsense) {
    __threadfence();
    __syncthreads();
    if (threadIdx.x == 0) {
        int s = (*lsense ^= 1);
        int old = atomicAdd(&g_bcount, 1);
        if (old == NB - 1) {
            g_bcount = 0;
            __threadfence();
            g_bsense = s;
        } else {
            while (g_bsense != s) __nanosleep(32);
            __threadfence();
        }
    }
    __syncthreads();
}

// ---------------- shared union ----------------
struct SharedGemm { float Xs[16][68]; float Ws[16][68]; };
struct SharedPred { float sA[64][68]; float sB[64][68]; float sW[64]; };
struct SharedScan { int psum[256]; };
union SharedU {
    SharedGemm g;
    SharedPred p;
    SharedScan s;
};

// ---------------- GEMM tile: C[64x64] at tile index, C = X@W (+bias) ----------------
// X [M,K] row-major, W [K,N] row-major, N multiple of 64, K multiple of 16.
__device__ void gemm_tile(const float* __restrict__ X, const float* __restrict__ W,
                          const float* __restrict__ bias, float* __restrict__ C,
                          int K, int N, int tile, SharedGemm& sg)
{
    int tiles_n = N >> 6;
    int m0 = (tile / tiles_n) << 6;
    int n0 = (tile % tiles_n) << 6;
    int t  = threadIdx.x;
    int tx = t & 15;
    int ty = t >> 4;

    float acc[4][4];
#pragma unroll
    for (int i = 0; i < 4; i++)
#pragma unroll
        for (int j = 0; j < 4; j++) acc[i][j] = 0.0f;

    int xk = t & 15;
    int xm = t >> 4;
    int wn = t & 63;
    int wk = t >> 6;

    for (int kt = 0; kt < K; kt += 16) {
#pragma unroll
        for (int it = 0; it < 4; it++) {
            int mm = xm + 16 * it;
            sg.Xs[xk][mm] = X[(m0 + mm) * K + kt + xk];
        }
#pragma unroll
        for (int it = 0; it < 4; it++) {
            int kk = wk + 4 * it;
            sg.Ws[kk][wn] = W[(kt + kk) * N + n0 + wn];
        }
        __syncthreads();
#pragma unroll
        for (int kk = 0; kk < 16; kk++) {
            float4 a = *(const float4*)&sg.Xs[kk][ty * 4];
            float4 b = *(const float4*)&sg.Ws[kk][tx * 4];
            acc[0][0] = fmaf(a.x, b.x, acc[0][0]);
            acc[0][1] = fmaf(a.x, b.y, acc[0][1]);
            acc[0][2] = fmaf(a.x, b.z, acc[0][2]);
            acc[0][3] = fmaf(a.x, b.w, acc[0][3]);
            acc[1][0] = fmaf(a.y, b.x, acc[1][0]);
            acc[1][1] = fmaf(a.y, b.y, acc[1][1]);
            acc[1][2] = fmaf(a.y, b.z, acc[1][2]);
            acc[1][3] = fmaf(a.y, b.w, acc[1][3]);
            acc[2][0] = fmaf(a.z, b.x, acc[2][0]);
            acc[2][1] = fmaf(a.z, b.y, acc[2][1]);
            acc[2][2] = fmaf(a.z, b.z, acc[2][2]);
            acc[2][3] = fmaf(a.z, b.w, acc[2][3]);
            acc[3][0] = fmaf(a.w, b.x, acc[3][0]);
            acc[3][1] = fmaf(a.w, b.y, acc[3][1]);
            acc[3][2] = fmaf(a.w, b.z, acc[3][2]);
            acc[3][3] = fmaf(a.w, b.w, acc[3][3]);
        }
        __syncthreads();
    }

    float4 bv = make_float4(0.f, 0.f, 0.f, 0.f);
    if (bias) bv = *(const float4*)&bias[n0 + tx * 4];
#pragma unroll
    for (int i = 0; i < 4; i++) {
        int m = m0 + ty * 4 + i;
        float4 o;
        o.x = acc[i][0] + bv.x;
        o.y = acc[i][1] + bv.y;
        o.z = acc[i][2] + bv.z;
        o.w = acc[i][3] + bv.w;
        *(float4*)&C[m * N + n0 + tx * 4] = o;
    }
}

// ---------------- aggregation phase ----------------
// out[n,f] = relu( h[n,f]*dis[n]^2 + sum_e h[src_e,f]*norm_e + b[f] )
// 4 nodes per block (64 lanes per node), nodes strided across grid.
__device__ void aggregate_phase(const float* __restrict__ h,
                                const float* __restrict__ bias,
                                float* __restrict__ xout)
{
    int t = threadIdx.x;
    int sub = t >> 6;
    int lane = t & 63;
    int f = lane * 4;
    float4 b = *(const float4*)&bias[f];

    for (int n = blockIdx.x * 4 + sub; n < N_N; n += NB * 4) {
        float dn = g_dis[n];
        float s2 = dn * dn;
        float4 hv = *(const float4*)&h[n * H_H + f];
        float4 acc;
        acc.x = hv.x * s2; acc.y = hv.y * s2; acc.z = hv.z * s2; acc.w = hv.w * s2;

        int beg = g_off[n], end = g_off[n + 1];
        int c = beg;
        for (; c + 4 <= end; c += 4) {
            int   i0 = g_csrc[c],     i1 = g_csrc[c + 1];
            int   i2 = g_csrc[c + 2], i3 = g_csrc[c + 3];
            float w0 = g_cnorm[c],     w1 = g_cnorm[c + 1];
            float w2 = g_cnorm[c + 2], w3 = g_cnorm[c + 3];
            float4 v0 = *(const float4*)&h[i0 * H_H + f];
            float4 v1 = *(const float4*)&h[i1 * H_H + f];
            float4 v2 = *(const float4*)&h[i2 * H_H + f];
            float4 v3 = *(const float4*)&h[i3 * H_H + f];
            acc.x = fmaf(v0.x, w0, acc.x); acc.y = fmaf(v0.y, w0, acc.y);
            acc.z = fmaf(v0.z, w0, acc.z); acc.w = fmaf(v0.w, w0, acc.w);
            acc.x = fmaf(v1.x, w1, acc.x); acc.y = fmaf(v1.y, w1, acc.y);
            acc.z = fmaf(v1.z, w1, acc.z); acc.w = fmaf(v1.w, w1, acc.w);
            acc.x = fmaf(v2.x, w2, acc.x); acc.y = fmaf(v2.y, w2, acc.y);
            acc.z = fmaf(v2.z, w2, acc.z); acc.w = fmaf(v2.w, w2, acc.w);
            acc.x = fmaf(v3.x, w3, acc.x); acc.y = fmaf(v3.y, w3, acc.y);
            acc.z = fmaf(v3.z, w3, acc.z); acc.w = fmaf(v3.w, w3, acc.w);
        }
        for (; c < end; c++) {
            int   i0 = g_csrc[c];
            float w0 = g_cnorm[c];
            float4 v0 = *(const float4*)&h[i0 * H_H + f];
            acc.x = fmaf(v0.x, w0, acc.x); acc.y = fmaf(v0.y, w0, acc.y);
            acc.z = fmaf(v0.z, w0, acc.z); acc.w = fmaf(v0.w, w0, acc.w);
        }
        float4 o;
        o.x = fmaxf(acc.x + b.x, 0.0f);
        o.y = fmaxf(acc.y + b.y, 0.0f);
        o.z = fmaxf(acc.z + b.z, 0.0f);
        o.w = fmaxf(acc.w + b.w, 0.0f);
        *(float4*)&xout[n * H_H + f] = o;
    }
}

// ---------------- predictor tile ----------------
__device__ void predict_tile(const float* __restrict__ Wq2, float bq2v,
                             float* __restrict__ out, int tile, SharedPred& sp)
{
    int u0 = (tile >> 4) << 6;    // 16 p-tiles per row
    int p0 = (tile & 15) << 6;
    int t  = threadIdx.x;
    int tx = t & 15;
    int ty = t >> 4;

    float acc[4][4];
#pragma unroll
    for (int i = 0; i < 4; i++)
#pragma unroll
        for (int j = 0; j < 4; j++) acc[i][j] = 0.0f;

    int lh = t & 63;
    int lr = t >> 6;

    for (int h0 = 0; h0 < H_H; h0 += 64) {
#pragma unroll
        for (int it = 0; it < 16; it++) {
            int r = lr + 4 * it;
            sp.sA[lh][r] = g_A[(u0 + r) * H_H + h0 + lh];
            sp.sB[lh][r] = g_B[(p0 + r) * H_H + h0 + lh];
        }
        if (t < 64) sp.sW[t] = Wq2[h0 + t];
        __syncthreads();
#pragma unroll
        for (int hh = 0; hh < 64; hh++) {
            float w = sp.sW[hh];
            float4 a = *(const float4*)&sp.sA[hh][ty * 4];
            float4 b = *(const float4*)&sp.sB[hh][tx * 4];
            float av[4] = {a.x, a.y, a.z, a.w};
            float bv[4] = {b.x, b.y, b.z, b.w};
#pragma unroll
            for (int i = 0; i < 4; i++)
#pragma unroll
                for (int j = 0; j < 4; j++) {
                    float v = fmaxf(av[i] + bv[j], 0.0f);
                    acc[i][j] = fmaf(v, w, acc[i][j]);
                }
        }
        __syncthreads();
    }

#pragma unroll
    for (int i = 0; i < 4; i++) {
        int u = u0 + ty * 4 + i;
        float4 o;
        o.x = 1.0f / (1.0f + __expf(-(acc[i][0] + bq2v)));
        o.y = 1.0f / (1.0f + __expf(-(acc[i][1] + bq2v)));
        o.z = 1.0f / (1.0f + __expf(-(acc[i][2] + bq2v)));
        o.w = 1.0f / (1.0f + __expf(-(acc[i][3] + bq2v)));
        *(float4*)&out[u * P_N + p0 + tx * 4] = o;
    }
}

// ---------------- the persistent mega-kernel ----------------
__global__ __launch_bounds__(NT, 1) void mega_kernel(
    const int* __restrict__ uid, const int* __restrict__ pid,
    const int* __restrict__ ei,
    const float* __restrict__ uemb, const float* __restrict__ pemb,
    const float* __restrict__ W0, const float* __restrict__ b0,
    const float* __restrict__ W1, const float* __restrict__ b1,
    const float* __restrict__ W2, const float* __restrict__ b2,
    const float* __restrict__ Wu, const float* __restrict__ bu,
    const float* __restrict__ Wp, const float* __restrict__ bp,
    const float* __restrict__ Wq1, const float* __restrict__ bq1,
    const float* __restrict__ Wq2, const float* __restrict__ bq2,
    float* __restrict__ out)
{
    __shared__ SharedU sh;
    int bid = blockIdx.x;
    int t   = threadIdx.x;
    int lsense = g_bsense;     // self-correcting initial sense (replay-safe)

    // ---- P0: weight composition + bcomb + zero deg + gather x0 ----
    if (bid < 16) {
        gemm_tile(Wu, Wq1, nullptr, g_WcU, D_D, H_H, bid, sh.g);
    } else if (bid < 32) {
        gemm_tile(Wp, Wq1 + D_D * H_H, nullptr, g_WcP, D_D, H_H, bid - 16, sh.g);
    } else if (bid == 32) {
        float acc = bq1[t];
#pragma unroll 4
        for (int k = 0; k < D_D; k++) acc = fmaf(bu[k], Wq1[k * H_H + t], acc);
        g_bcU[t] = acc;
    } else if (bid == 33) {
        float acc = 0.0f;
#pragma unroll 4
        for (int k = 0; k < D_D; k++) acc = fmaf(bp[k], Wq1[(D_D + k) * H_H + t], acc);
        g_bcP[t] = acc;
    } else if (bid < 36) {
        // FULL coverage of g_deg (replay-critical: graph replays reuse state)
        for (int i = (bid - 34) * NT + t; i < N_N; i += 2 * NT)
            g_deg[i] = 0;
    } else {
        // gather x0 over blocks 36..147 (112 blocks)
        for (int idx = (bid - 36) * NT + t; idx < N_N * (D_D / 4); idx += 112 * NT) {
            int i  = idx >> 5;
            int dd = (idx & 31) * 4;
            float4 v;
            if (i < U_N) v = *(const float4*)&uemb[uid[i] * D_D + dd];
            else         v = *(const float4*)&pemb[pid[i - U_N] * D_D + dd];
            *(float4*)&g_x0[i * D_D + dd] = v;
        }
    }
    gsync(&lsense);

    // ---- P1: count + rank ----
    for (int e = bid * NT + t; e < E_E; e += NB * NT) {
        int d = ei[E_E + e];
        g_rank[e] = atomicAdd(&g_deg[d], 1);
    }
    gsync(&lsense);

    // ---- P2: block 0 scans offsets; blocks 1..147 compute dis in parallel ----
    if (bid == 0) {
        int i0 = t * 6;
        int v[6];
        int loc = 0;
#pragma unroll
        for (int j = 0; j < 6; j++) {
            int dg = g_deg[i0 + j];
            v[j] = dg;
            loc += dg;
        }
        sh.s.psum[t] = loc;
        __syncthreads();
        for (int off = 1; off < 256; off <<= 1) {
            int pv = 0;
            if (t >= off) pv = sh.s.psum[t - off];
            __syncthreads();
            sh.s.psum[t] += pv;
            __syncthreads();
        }
        int run = sh.s.psum[t] - loc;
#pragma unroll
        for (int j = 0; j < 6; j++) {
            g_off[i0 + j] = run;
            run += v[j];
        }
        if (t == 255) g_off[N_N] = run;
    } else {
        for (int i = (bid - 1) * NT + t; i < N_N; i += 147 * NT)
            g_dis[i] = rsqrtf((float)(g_deg[i] + 1));   // +1 self loop
    }
    gsync(&lsense);

    // ---- P3: scatter (pure stores, rank-based) ----
    for (int e = bid * NT + t; e < E_E; e += NB * NT) {
        int s = ei[e];
        int d = ei[E_E + e];
        int slot = g_off[d] + g_rank[e];
        g_csrc[slot]  = s;
        g_cnorm[slot] = g_dis[s] * g_dis[d];
    }
    gsync(&lsense);

    // ---- P4/P5 .. P8/P9: 3 x (GEMM + aggregate) ----
    for (int tile = bid; tile < (N_N / 64) * (H_H / 64); tile += NB)
        gemm_tile(g_x0, W0, nullptr, g_h0, D_D, H_H, tile, sh.g);
    gsync(&lsense);
    aggregate_phase(g_h0, b0, g_xa);
    gsync(&lsense);

    for (int tile = bid; tile < (N_N / 64) * (H_H / 64); tile += NB)
        gemm_tile(g_xa, W1, nullptr, g_h1, H_H, H_H, tile, sh.g);
    gsync(&lsense);
    aggregate_phase(g_h1, b1, g_xb);
    gsync(&lsense);

    for (int tile = bid; tile < (N_N / 64) * (H_H / 64); tile += NB)
        gemm_tile(g_xb, W2, nullptr, g_h2, H_H, H_H, tile, sh.g);
    gsync(&lsense);
    aggregate_phase(g_h2, b2, g_xc);
    gsync(&lsense);

    // ---- P10: A = xc_u @ WcU + bcU ; B = xc_p @ WcP + bcP ----
    {
        const int tiles_A = (U_N / 64) * (H_H / 64);   // 32
        const int tiles_B = (P_N / 64) * (H_H / 64);   // 64
        for (int tile = bid; tile < tiles_A + tiles_B; tile += NB) {
            if (tile < tiles_A)
                gemm_tile(g_xc, g_WcU, g_bcU, g_A, H_H, H_H, tile, sh.g);
            else
                gemm_tile(g_xc + U_N * H_H, g_WcP, g_bcP, g_B, H_H, H_H,
                          tile - tiles_A, sh.g);
        }
    }
    gsync(&lsense);

    // ---- P11: predictor (128 tiles) ----
    float bq2v = bq2[0];
    for (int tile = bid; tile < (U_N / 64) * (P_N / 64); tile += NB)
        predict_tile(Wq2, bq2v, out, tile, sh.p);
    // no trailing barrier needed: sense self-corrects at next launch
}

// ---------------- launch ----------------
extern "C" void kernel_launch(void* const* d_in, const int* in_sizes, int n_in,
                              void* d_out, int out_size)
{
    const int*   uid  = (const int*)  d_in[0];
    const int*   pid  = (const int*)  d_in[1];
    const int*   ei   = (const int*)  d_in[2];
    // d_in[3] = user_paper_interactions (unused by reference)
    const float* uemb = (const float*)d_in[4];
    const float* pemb = (const float*)d_in[5];
    const float* W0   = (const float*)d_in[6];
    const float* b0   = (const float*)d_in[7];
    const float* W1   = (const float*)d_in[8];
    const float* b1   = (const float*)d_in[9];
    const float* W2   = (const float*)d_in[10];
    const float* b2   = (const float*)d_in[11];
    const float* Wu   = (const float*)d_in[12];
    const float* bu   = (const float*)d_in[13];
    const float* Wp   = (const float*)d_in[14];
    const float* bp   = (const float*)d_in[15];
    const float* Wq1  = (const float*)d_in[16];
    const float* bq1  = (const float*)d_in[17];
    const float* Wq2  = (const float*)d_in[18];
    const float* bq2  = (const float*)d_in[19];
    float* out = (float*)d_out;

    mega_kernel<<<NB, NT>>>(uid, pid, ei, uemb, pemb,
                            W0, b0, W1, b1, W2, b2,
                            Wu, bu, Wp, bp, Wq1, bq1, Wq2, bq2, out);
}

// round 17
// speedup vs baseline: 1.3321x; 1.3321x over previous
#include <cuda_runtime.h>
#include <math.h>

// Problem constants
#define U_N 512
#define P_N 1024
#define N_N 1536
#define D_D 128
#define H_H 256
#define E_E 98304

// ---------------- scratch (static __device__, no allocs) ----------------
__device__ int   g_deg[N_N];
__device__ float g_dis[N_N];
__device__ int   g_off[N_N + 1];
__device__ int   g_rank[E_E];
__device__ int   g_csrc[E_E];
__device__ float g_cnorm[E_E];
__device__ float g_x0[N_N * D_D];
__device__ float g_h [N_N * H_H];
__device__ float g_x [N_N * H_H];
__device__ float g_WcU[H_H * H_H];   // Wu @ Wq1_top  [256,256]
__device__ float g_WcP[H_H * H_H];   // Wp @ Wq1_bot  [256,256]
__device__ float g_bcU[H_H];         // bu @ Wq1_top + bq1
__device__ float g_bcP[H_H];         // bp @ Wq1_bot
__device__ float g_A[U_N * H_H];
__device__ float g_B[P_N * H_H];

// ---------------- device GEMM tile helper (linearized tile index) ----------------
// C[64x64 tile] = X[M,K] @ W[K,N] (+bias). N mult of 64, K mult of 16.
__device__ __forceinline__ void gemm_device(
    const float* __restrict__ X, const float* __restrict__ W,
    const float* __restrict__ bias, float* __restrict__ C,
    int K, int N, int tile)
{
    __shared__ float Xs[16][68];
    __shared__ float Ws[16][68];

    int tiles_n = N >> 6;
    int m0 = (tile / tiles_n) << 6;
    int n0 = (tile % tiles_n) << 6;
    int t  = threadIdx.x;
    int tx = t & 15;
    int ty = t >> 4;

    float acc[4][4];
#pragma unroll
    for (int i = 0; i < 4; i++)
#pragma unroll
        for (int j = 0; j < 4; j++) acc[i][j] = 0.0f;

    int xk = t & 15;
    int xm = t >> 4;
    int wn = t & 63;
    int wk = t >> 6;

    for (int kt = 0; kt < K; kt += 16) {
#pragma unroll
        for (int it = 0; it < 4; it++) {
            int mm = xm + 16 * it;
            Xs[xk][mm] = X[(m0 + mm) * K + kt + xk];
        }
#pragma unroll
        for (int it = 0; it < 4; it++) {
            int kk = wk + 4 * it;
            Ws[kk][wn] = W[(kt + kk) * N + n0 + wn];
        }
        __syncthreads();
#pragma unroll
        for (int kk = 0; kk < 16; kk++) {
            float4 a = *(const float4*)&Xs[kk][ty * 4];
            float4 b = *(const float4*)&Ws[kk][tx * 4];
            acc[0][0] = fmaf(a.x, b.x, acc[0][0]);
            acc[0][1] = fmaf(a.x, b.y, acc[0][1]);
            acc[0][2] = fmaf(a.x, b.z, acc[0][2]);
            acc[0][3] = fmaf(a.x, b.w, acc[0][3]);
            acc[1][0] = fmaf(a.y, b.x, acc[1][0]);
            acc[1][1] = fmaf(a.y, b.y, acc[1][1]);
            acc[1][2] = fmaf(a.y, b.z, acc[1][2]);
            acc[1][3] = fmaf(a.y, b.w, acc[1][3]);
            acc[2][0] = fmaf(a.z, b.x, acc[2][0]);
            acc[2][1] = fmaf(a.z, b.y, acc[2][1]);
            acc[2][2] = fmaf(a.z, b.z, acc[2][2]);
            acc[2][3] = fmaf(a.z, b.w, acc[2][3]);
            acc[3][0] = fmaf(a.w, b.x, acc[3][0]);
            acc[3][1] = fmaf(a.w, b.y, acc[3][1]);
            acc[3][2] = fmaf(a.w, b.z, acc[3][2]);
            acc[3][3] = fmaf(a.w, b.w, acc[3][3]);
        }
        __syncthreads();
    }

    float4 bv = make_float4(0.f, 0.f, 0.f, 0.f);
    if (bias) bv = *(const float4*)&bias[n0 + tx * 4];
#pragma unroll
    for (int i = 0; i < 4; i++) {
        int m = m0 + ty * 4 + i;
        float4 o;
        o.x = acc[i][0] + bv.x;
        o.y = acc[i][1] + bv.y;
        o.z = acc[i][2] + bv.z;
        o.w = acc[i][3] + bv.w;
        *(float4*)&C[m * N + n0 + tx * 4] = o;
    }
}

// ---------------- K1: zero degree ----------------
__global__ void zero_kernel() {
    int i = blockIdx.x * 256 + threadIdx.x;
    if (i < N_N) g_deg[i] = 0;
}

// ---------------- K2: fused build (count+rank | gather x0 | Wc GEMMs | bias folds) ----
// grid = 610 blocks x 256 threads
__global__ __launch_bounds__(256) void build_kernel(
    const int* __restrict__ ei,
    const int* __restrict__ uid, const int* __restrict__ pid,
    const float* __restrict__ uemb, const float* __restrict__ pemb,
    const float* __restrict__ Wu, const float* __restrict__ bu,
    const float* __restrict__ Wp, const float* __restrict__ bp,
    const float* __restrict__ Wq1, const float* __restrict__ bq1)
{
    int bid = blockIdx.x;
    int t   = threadIdx.x;

    if (bid < 384) {
        // count + rank (E_E = 384*256 exactly)
        int e = bid * 256 + t;
        int d = ei[E_E + e];
        g_rank[e] = atomicAdd(&g_deg[d], 1);
    } else if (bid < 576) {
        // gather x0: 1536*32 float4s over 192 blocks exactly
        int idx = (bid - 384) * 256 + t;
        int i  = idx >> 5;
        int dd = (idx & 31) * 4;
        float4 v;
        if (i < U_N) v = *(const float4*)&uemb[uid[i] * D_D + dd];
        else         v = *(const float4*)&pemb[pid[i - U_N] * D_D + dd];
        *(float4*)&g_x0[i * D_D + dd] = v;
    } else if (bid < 608) {
        // weight composition: WcU = Wu @ Wq1_top, WcP = Wp @ Wq1_bot  (16 tiles each)
        bool isU = bid < 592;
        const float* X = isU ? Wu : Wp;                      // [256,128]
        const float* W = isU ? Wq1 : (Wq1 + D_D * H_H);      // [128,256]
        float*       C = isU ? g_WcU : g_WcP;
        int tile = isU ? (bid - 576) : (bid - 592);
        gemm_device(X, W, nullptr, C, D_D, H_H, tile);
    } else if (bid == 608) {
        float acc = bq1[t];
#pragma unroll 4
        for (int k = 0; k < D_D; k++) acc = fmaf(bu[k], Wq1[k * H_H + t], acc);
        g_bcU[t] = acc;
    } else {
        float acc = 0.0f;
#pragma unroll 4
        for (int k = 0; k < D_D; k++) acc = fmaf(bp[k], Wq1[(D_D + k) * H_H + t], acc);
        g_bcP[t] = acc;
    }
}

// ---------------- K3: scan (single block, 512 threads) — offsets + dis ----------------
__global__ void scan_kernel() {
    __shared__ int vals[N_N];
    __shared__ int psum[512];
    int t = threadIdx.x;
    for (int i = t; i < N_N; i += 512) {
        int v = g_deg[i];
        vals[i] = v;
        g_dis[i] = rsqrtf((float)(v + 1));   // +1 self loop
    }
    __syncthreads();
    int base = t * 3;
    int s0 = vals[base], s1 = vals[base + 1], s2 = vals[base + 2];
    int loc = s0 + s1 + s2;
    psum[t] = loc;
    __syncthreads();
    for (int off = 1; off < 512; off <<= 1) {
        int v = 0;
        if (t >= off) v = psum[t - off];
        __syncthreads();
        psum[t] += v;
        __syncthreads();
    }
    int excl = psum[t] - loc;
    g_off[base]     = excl;
    g_off[base + 1] = excl + s0;
    g_off[base + 2] = excl + s0 + s1;
    if (t == 511) g_off[N_N] = psum[511];
}

// ---------------- K4: scatter (pure stores, rank-based) ----------------
__global__ void scatter_kernel(const int* __restrict__ ei) {
    int e = blockIdx.x * 256 + threadIdx.x;
    int s = ei[e];
    int d = ei[E_E + e];
    int slot = g_off[d] + g_rank[e];
    g_csrc[slot]  = s;
    g_cnorm[slot] = g_dis[s] * g_dis[d];
}

// ---------------- standalone SGEMM (proven, from the 159.5us run) ----------------
__global__ __launch_bounds__(256) void sgemm_kernel(
    const float* __restrict__ X, const float* __restrict__ W,
    const float* __restrict__ bias, float* __restrict__ C,
    int M, int K, int N)
{
    int tiles_n = N >> 6;
    int tile = blockIdx.y * tiles_n + blockIdx.x;
    gemm_device(X, W, bias, C, K, N, tile);
}

// ---------------- K11: fused A/B GEMMs (96 tiles) ----------------
__global__ __launch_bounds__(256) void ab_kernel() {
    int bid = blockIdx.x;
    if (bid < 32) {
        // A[512,256] = x_u @ WcU + bcU
        gemm_device(g_x, g_WcU, g_bcU, g_A, H_H, H_H, bid);
    } else {
        // B[1024,256] = x_p @ WcP + bcP
        gemm_device(g_x + U_N * H_H, g_WcP, g_bcP, g_B, H_H, H_H, bid - 32);
    }
}

// ---------------- GCN aggregation (proven, from the 159.5us run) ----------------
// out[n,f] = relu( h[n,f]*dis[n]^2 + sum_e h[src_e,f]*norm_e + b[f] )
__global__ __launch_bounds__(64) void aggregate_kernel(
    const float* __restrict__ h, const float* __restrict__ bias,
    float* __restrict__ xout)
{
    __shared__ int   ssrc[64];
    __shared__ float snorm[64];
    int n = blockIdx.x;
    int t = threadIdx.x;           // 0..63
    int f = t * 4;
    float dn = g_dis[n];
    float s2 = dn * dn;
    float4 hv = *(const float4*)&h[n * H_H + f];
    float4 acc;
    acc.x = hv.x * s2; acc.y = hv.y * s2; acc.z = hv.z * s2; acc.w = hv.w * s2;

    int beg = g_off[n], end = g_off[n + 1];
    for (int c = beg; c < end; c += 64) {
        int cnt = min(64, end - c);
        if (t < cnt) { ssrc[t] = g_csrc[c + t]; snorm[t] = g_cnorm[c + t]; }
        __syncthreads();
#pragma unroll 4
        for (int k = 0; k < cnt; k++) {
            float  w = snorm[k];
            float4 v = *(const float4*)&h[ssrc[k] * H_H + f];
            acc.x = fmaf(v.x, w, acc.x);
            acc.y = fmaf(v.y, w, acc.y);
            acc.z = fmaf(v.z, w, acc.z);
            acc.w = fmaf(v.w, w, acc.w);
        }
        __syncthreads();
    }
    float4 b = *(const float4*)&bias[f];
    float4 o;
    o.x = fmaxf(acc.x + b.x, 0.0f);
    o.y = fmaxf(acc.y + b.y, 0.0f);
    o.z = fmaxf(acc.z + b.z, 0.0f);
    o.w = fmaxf(acc.w + b.w, 0.0f);
    *(float4*)&xout[n * H_H + f] = o;
}

// ---------------- fused predictor (proven, from the 159.5us run) ----------------
// pred[u,p] = sigmoid( sum_h relu(A[u,h]+B[p,h]) * Wq2[h] + bq2 )
__global__ __launch_bounds__(256) void predict_kernel(
    const float* __restrict__ Wq2, const float* __restrict__ bq2,
    float* __restrict__ out)
{
    __shared__ float sA[64][68];   // [h][u]
    __shared__ float sB[64][68];   // [h][p]
    __shared__ float sW[64];

    int t  = threadIdx.x;
    int tx = t & 15;   // paper micro
    int ty = t >> 4;   // user micro
    int u0 = blockIdx.y * 64;
    int p0 = blockIdx.x * 64;

    float acc[4][4];
#pragma unroll
    for (int i = 0; i < 4; i++)
#pragma unroll
        for (int j = 0; j < 4; j++) acc[i][j] = 0.0f;

    int lh = t & 63;   // h for loads (coalesced)
    int lr = t >> 6;   // row base

    for (int h0 = 0; h0 < H_H; h0 += 64) {
#pragma unroll
        for (int it = 0; it < 16; it++) {
            int r = lr + 4 * it;
            sA[lh][r] = g_A[(u0 + r) * H_H + h0 + lh];
            sB[lh][r] = g_B[(p0 + r) * H_H + h0 + lh];
        }
        if (t < 64) sW[t] = Wq2[h0 + t];
        __syncthreads();
#pragma unroll
        for (int hh = 0; hh < 64; hh++) {
            float w = sW[hh];
            float4 a = *(const float4*)&sA[hh][ty * 4];
            float4 b = *(const float4*)&sB[hh][tx * 4];
            float av[4] = {a.x, a.y, a.z, a.w};
            float bv[4] = {b.x, b.y, b.z, b.w};
#pragma unroll
            for (int i = 0; i < 4; i++)
#pragma unroll
                for (int j = 0; j < 4; j++) {
                    float v = fmaxf(av[i] + bv[j], 0.0f);
                    acc[i][j] = fmaf(v, w, acc[i][j]);
                }
        }
        __syncthreads();
    }

    float c = bq2[0];
#pragma unroll
    for (int i = 0; i < 4; i++) {
        int u = u0 + ty * 4 + i;
        float4 o;
        o.x = 1.0f / (1.0f + __expf(-(acc[i][0] + c)));
        o.y = 1.0f / (1.0f + __expf(-(acc[i][1] + c)));
        o.z = 1.0f / (1.0f + __expf(-(acc[i][2] + c)));
        o.w = 1.0f / (1.0f + __expf(-(acc[i][3] + c)));
        *(float4*)&out[u * P_N + p0 + tx * 4] = o;
    }
}

// ---------------- launch (12 kernels) ----------------
extern "C" void kernel_launch(void* const* d_in, const int* in_sizes, int n_in,
                              void* d_out, int out_size)
{
    const int*   uid  = (const int*)  d_in[0];
    const int*   pid  = (const int*)  d_in[1];
    const int*   ei   = (const int*)  d_in[2];
    // d_in[3] = user_paper_interactions (unused by reference)
    const float* uemb = (const float*)d_in[4];
    const float* pemb = (const float*)d_in[5];
    const float* W0   = (const float*)d_in[6];
    const float* b0   = (const float*)d_in[7];
    const float* W1   = (const float*)d_in[8];
    const float* b1   = (const float*)d_in[9];
    const float* W2   = (const float*)d_in[10];
    const float* b2   = (const float*)d_in[11];
    const float* Wu   = (const float*)d_in[12];
    const float* bu   = (const float*)d_in[13];
    const float* Wp   = (const float*)d_in[14];
    const float* bp   = (const float*)d_in[15];
    const float* Wq1  = (const float*)d_in[16];
    const float* bq1  = (const float*)d_in[17];
    const float* Wq2  = (const float*)d_in[18];
    const float* bq2  = (const float*)d_in[19];
    float* out = (float*)d_out;

    float *x0, *h, *x;
    cudaGetSymbolAddress((void**)&x0, g_x0);
    cudaGetSymbolAddress((void**)&h,  g_h);
    cudaGetSymbolAddress((void**)&x,  g_x);

    // graph build + weight composition (overlapped)
    zero_kernel<<<6, 256>>>();
    build_kernel<<<610, 256>>>(ei, uid, pid, uemb, pemb, Wu, bu, Wp, bp, Wq1, bq1);
    scan_kernel<<<1, 512>>>();
    scatter_kernel<<<384, 256>>>(ei);

    // 3 GCN layers
    sgemm_kernel<<<dim3(H_H / 64, N_N / 64), 256>>>(x0, W0, nullptr, h, N_N, D_D, H_H);
    aggregate_kernel<<<N_N, 64>>>(h, b0, x);
    sgemm_kernel<<<dim3(H_H / 64, N_N / 64), 256>>>(x, W1, nullptr, h, N_N, H_H, H_H);
    aggregate_kernel<<<N_N, 64>>>(h, b1, x);
    sgemm_kernel<<<dim3(H_H / 64, N_N / 64), 256>>>(x, W2, nullptr, h, N_N, H_H, H_H);
    aggregate_kernel<<<N_N, 64>>>(h, b2, x);

    // A/B with pre-composed weights (one fused launch)
    ab_kernel<<<96, 256>>>();

    // predictor
    predict_kernel<<<dim3(P_N / 64, U_N / 64), 256>>>(Wq2, bq2, out);
}